// round 15
// baseline (speedup 1.0000x reference)
#include <cuda_runtime.h>
#include <cuda_fp16.h>
#include <cstddef>

#define N_SRC   16384
#define N_TGT   65536
#define KNBR    8
#define CCH     16
#define CSKIP   2
#define SSC     32
#define HID     64
#define MVD     16
#define ROW_MV  (CCH*MVD)      // 256
#define TPB     128
#define TGT_PER_BLOCK 16
#define HA_STRIDE 68
#define SK_STRIDE 36
#define PREP_ROWS 32           // source rows per block -> 512 blocks (single wave)

__device__ __half g_mvTh[(size_t)N_SRC * ROW_MV]; // mv_src @ Weff[0:16]  (8 MB fp16)
__device__ __half g_scTh[(size_t)N_SRC * HID];    // sc_src @ W1a         (2 MB fp16)
__device__ __half g_w1bh[SSC * HID];              // W1_s rows 32..63 fp16
__device__ __half g_w2p[HID * SSC];               // W2 packed: [hc][ch][r] fp16
__device__ float  g_wsk[2 * CCH];                 // Weff rows 16,17

typedef unsigned long long ull;

__device__ __forceinline__ ull pack2(float lo, float hi)
{
    ull r;
    asm("mov.b64 %0, {%1, %2};" : "=l"(r) : "r"(__float_as_uint(lo)), "r"(__float_as_uint(hi)));
    return r;
}
__device__ __forceinline__ void unpack2(ull v, float& lo, float& hi)
{
    unsigned a, b;
    asm("mov.b64 {%0, %1}, %2;" : "=r"(a), "=r"(b) : "l"(v));
    lo = __uint_as_float(a);
    hi = __uint_as_float(b);
}
__device__ __forceinline__ void ffma2(ull& d, ull a, ull b)
{
    asm("fma.rn.f32x2 %0, %1, %2, %3;" : "=l"(d) : "l"(a), "l"(b), "l"(d));
}

__device__ __forceinline__ float gelu_tanh(float x)
{
    const float c0 = 0.7978845608028654f;
    float u = c0 * fmaf(0.044715f * x, x * x, x);
    float t = tanhf(u);
    return 0.5f * x * (1.0f + t);
}

// ---------------------------------------------------------------------------
// Prep: 512 blocks x 256 thr, 32 rows each. Transforms in fma.rn.f32x2.
// ---------------------------------------------------------------------------
__global__ __launch_bounds__(256) void prep_all(
    const float* __restrict__ mv_src, const float* __restrict__ sc_src,
    const float* __restrict__ W1_mv,  const float* __restrict__ W2_mv,
    const float* __restrict__ W1_s,   const float* __restrict__ W2_s)
{
    __shared__ __align__(16) float rows[8 * 256];        // 8 KB (chunk of 8 rows)
    __shared__ __align__(16) float we[CCH * CCH];        // 1 KB
    __shared__ __align__(16) float xs[PREP_ROWS * 34];   // 4.25 KB (stride 34: pairs 8B-aligned)
    __shared__ __align__(16) float wT[HID * 34];         // 8.5 KB  W1a transposed [h][j], j<32
    __shared__ __align__(16) float w2T[CCH * 66];        // 4.1 KB  W2_mv transposed [c][h], h<64

    const int tid = threadIdx.x;
    const int s0  = blockIdx.x * PREP_ROWS;

    // ---- stage everything (coalesced reads) ----
    const float4* msrc = (const float4*)(mv_src + (size_t)s0 * 256);
    ((float4*)rows)[tid]       = __ldg(msrc + tid);           // chunk 0 (rows 0..7)
    ((float4*)rows)[tid + 256] = __ldg(msrc + tid + 256);
    #pragma unroll
    for (int i = 0; i < 4; i++) {                             // xs: 1024 floats
        const int idx = tid + 256 * i;
        xs[(idx >> 5) * 34 + (idx & 31)] = __ldg(sc_src + (size_t)s0 * SSC + idx);
    }
    #pragma unroll
    for (int i = 0; i < 8; i++) {                             // wT: W1a transposed [h][j]
        const int idx = tid + 256 * i;                        // j = idx>>6, h = idx&63
        wT[(idx & 63) * 34 + (idx >> 6)] = __ldg(W1_s + idx);
    }
    #pragma unroll
    for (int i = 0; i < 4; i++) {                             // w2T: W2_mv transposed [c][h]
        const int idx = tid + 256 * i;                        // h = idx>>4, c = idx&15
        w2T[(idx & 15) * 66 + (idx >> 4)] = __ldg(W2_mv + idx);
    }
    if (blockIdx.x == 0) {                                    // weight side-products
        #pragma unroll
        for (int i = 0; i < 8; i++) {
            const int idx = tid + 256 * i;                    // 0..2047
            g_w1bh[idx] = __float2half_rn(__ldg(W1_s + SSC * HID + idx));
            const int hc = idx >> 8, ch = (idx >> 3) & 31, r = idx & 7;
            g_w2p[idx] = __float2half_rn(__ldg(W2_s + (hc * 8 + r) * SSC + ch));
        }
        if (tid < 32) {
            const int cp = 16 + (tid >> 4), c = tid & 15;
            float acc = 0.f;
            #pragma unroll
            for (int h = 0; h < HID; h++)
                acc = fmaf(__ldg(W1_mv + cp * HID + h), __ldg(W2_mv + h * CCH + c), acc);
            g_wsk[tid] = acc;
        }
    }
    __syncthreads();

    // ---- Weff (f32x2, h-paired) + prefetch chunk 1 ----
    float4 pf0 = __ldg(msrc + 512 + tid);
    float4 pf1 = __ldg(msrc + 512 + tid + 256);
    {
        const int cp = tid >> 4, c = tid & 15;
        ull a2 = 0ULL;
        #pragma unroll
        for (int hp = 0; hp < 32; hp++) {
            ull w1p = __ldg((const ull*)(W1_mv + cp * HID + 2 * hp));
            ull w2p = *(const ull*)(w2T + c * 66 + 2 * hp);
            ffma2(a2, w1p, w2p);
        }
        float e, o;
        unpack2(a2, e, o);
        we[tid] = e + o;
    }
    __syncthreads();

    // ---- mvT: 4 chunks of 8 rows (warp per row; f32x2 on pre-packed LDS.128) ----
    const int mrow = tid >> 5;
    const int c2   = (tid & 31) >> 1;
    const int i0   = (tid & 1) * 8;
    #pragma unroll
    for (int ch = 0; ch < 4; ch++) {
        {   // compute current chunk
            const float* row = rows + mrow * 256;
            ull acc2[4] = {0ULL, 0ULL, 0ULL, 0ULL};
            #pragma unroll
            for (int cp = 0; cp < 16; cp++) {
                const ull wv2 = pack2(we[cp * 16 + c2], we[cp * 16 + c2]);
                const ulonglong2* rp = (const ulonglong2*)(row + cp * 16 + i0);
                ulonglong2 pa = rp[0], pb = rp[1];
                ffma2(acc2[0], pa.x, wv2);
                ffma2(acc2[1], pa.y, wv2);
                ffma2(acc2[2], pb.x, wv2);
                ffma2(acc2[3], pb.y, wv2);
            }
            __half2 h2[4];
            #pragma unroll
            for (int p = 0; p < 4; p++) {
                float lo, hi;
                unpack2(acc2[p], lo, hi);
                h2[p] = __floats2half2_rn(lo, hi);
            }
            *(uint4*)(g_mvTh + (size_t)(s0 + ch * 8 + mrow) * 256 + c2 * 16 + i0) =
                *(const uint4*)h2;
        }
        if (ch < 3) {
            __syncthreads();   // everyone done reading rows
            ((float4*)rows)[tid]       = pf0;
            ((float4*)rows)[tid + 256] = pf1;
            if (ch < 2) {      // prefetch chunk ch+2
                pf0 = __ldg(msrc + 512 * (ch + 2) + tid);
                pf1 = __ldg(msrc + 512 * (ch + 2) + tid + 256);
            }
            __syncthreads();   // rows ready
        }
    }

    // ---- scT (f32x2, j-paired over transposed weights) ----
    // thread -> h = tid&63; row-group rg = tid>>6 handles rows rg*8 .. rg*8+7
    {
        const int h  = tid & 63;
        const int rg = tid >> 6;
        #pragma unroll
        for (int half = 0; half < 2; half++) {
            const int rb = rg * 8 + half * 4;
            ull acc2[4] = {0ULL, 0ULL, 0ULL, 0ULL};
            #pragma unroll
            for (int jp = 0; jp < 16; jp++) {
                const ull wp = *(const ull*)(wT + h * 34 + 2 * jp);
                #pragma unroll
                for (int r = 0; r < 4; r++) {
                    const ull xp = *(const ull*)(xs + (rb + r) * 34 + 2 * jp);
                    ffma2(acc2[r], xp, wp);
                }
            }
            #pragma unroll
            for (int r = 0; r < 4; r++) {
                float e, o;
                unpack2(acc2[r], e, o);
                g_scTh[(size_t)(s0 + rb + r) * HID + h] = __float2half_rn(e + o);
            }
        }
    }
}

// ---------------------------------------------------------------------------
// Warp-private pipeline (unchanged from R13; fused ~61us measured)
// ---------------------------------------------------------------------------
__global__ __launch_bounds__(TPB, 6) void fused_kernel(
    const float* __restrict__ mv_skip, const float* __restrict__ sc_skip,
    const float* __restrict__ pos_src, const float* __restrict__ pos_tgt,
    const int*   __restrict__ isrc,
    const float* __restrict__ b1_s,    const float* __restrict__ b2_s,
    float* __restrict__ out_mv,        float* __restrict__ out_sc)
{
    __shared__ __align__(16) float sHA[TGT_PER_BLOCK * HA_STRIDE];
    __shared__ __align__(16) float sSK[TGT_PER_BLOCK * SK_STRIDE];

    const int tid  = threadIdx.x;
    const int lane = tid & 31;
    const int warp = tid >> 5;
    const int tbase = blockIdx.x * TGT_PER_BLOCK;
    const int r0 = warp * 4;

    const int cch = lane >> 1;
    const float w16 = __ldg(g_wsk + cch);
    const float w17 = __ldg(g_wsk + 16 + cch);

    float hh0[4], hh1[4];

    // ---------------- Phase 1: IDW gather of fp16 transformed sources -------
    #pragma unroll
    for (int u = 0; u < 4; u++) {
        const int tl = r0 + u;
        const int t  = tbase + tl;

        float wk = 0.f;
        int   sk = 0;
        if (lane < KNBR) {
            sk = isrc[t * KNBR + lane];
            float dx = pos_src[sk * 3 + 0] - pos_tgt[t * 3 + 0];
            float dy = pos_src[sk * 3 + 1] - pos_tgt[t * 3 + 1];
            float dz = pos_src[sk * 3 + 2] - pos_tgt[t * 3 + 2];
            float d2 = fmaf(dx, dx, fmaf(dy, dy, dz * dz));
            d2 = fmaxf(d2, 1e-16f);
            wk = 1.0f / d2;
        }
        float den = wk;
        #pragma unroll
        for (int o = 16; o; o >>= 1) den += __shfl_xor_sync(0xffffffffu, den, o);
        const float invd = 1.0f / den;

        float acc[8];
        #pragma unroll
        for (int j = 0; j < 8; j++) acc[j] = 0.f;
        float h0 = 0.f, h1 = 0.f;

        #pragma unroll
        for (int k = 0; k < KNBR; k++) {
            const float w = __shfl_sync(0xffffffffu, wk, k);
            const int   s = __shfl_sync(0xffffffffu, sk, k);
            uint4 v = __ldg((const uint4*)(g_mvTh + (size_t)s * ROW_MV) + lane);
            const __half2* hv = (const __half2*)&v;
            float2 f0 = __half22float2(hv[0]);
            float2 f1 = __half22float2(hv[1]);
            float2 f2 = __half22float2(hv[2]);
            float2 f3 = __half22float2(hv[3]);
            acc[0] = fmaf(w, f0.x, acc[0]); acc[1] = fmaf(w, f0.y, acc[1]);
            acc[2] = fmaf(w, f1.x, acc[2]); acc[3] = fmaf(w, f1.y, acc[3]);
            acc[4] = fmaf(w, f2.x, acc[4]); acc[5] = fmaf(w, f2.y, acc[5]);
            acc[6] = fmaf(w, f3.x, acc[6]); acc[7] = fmaf(w, f3.y, acc[7]);
            __half2 sv = __ldg((const __half2*)(g_scTh + (size_t)s * HID) + lane);
            float2 sf = __half22float2(sv);
            h0 = fmaf(w, sf.x, h0); h1 = fmaf(w, sf.y, h1);
        }

        const int ib = (lane & 1) * 8;
        float4 s0a = __ldg((const float4*)(mv_skip + (size_t)t * 32 + ib));
        float4 s0b = __ldg((const float4*)(mv_skip + (size_t)t * 32 + ib + 4));
        float4 s1a = __ldg((const float4*)(mv_skip + (size_t)t * 32 + 16 + ib));
        float4 s1b = __ldg((const float4*)(mv_skip + (size_t)t * 32 + 16 + ib + 4));

        float4 o0, o1;
        o0.x = fmaf(acc[0], invd, fmaf(s0a.x, w16, s1a.x * w17));
        o0.y = fmaf(acc[1], invd, fmaf(s0a.y, w16, s1a.y * w17));
        o0.z = fmaf(acc[2], invd, fmaf(s0a.z, w16, s1a.z * w17));
        o0.w = fmaf(acc[3], invd, fmaf(s0a.w, w16, s1a.w * w17));
        o1.x = fmaf(acc[4], invd, fmaf(s0b.x, w16, s1b.x * w17));
        o1.y = fmaf(acc[5], invd, fmaf(s0b.y, w16, s1b.y * w17));
        o1.z = fmaf(acc[6], invd, fmaf(s0b.z, w16, s1b.z * w17));
        o1.w = fmaf(acc[7], invd, fmaf(s0b.w, w16, s1b.w * w17));

        float4* dst = (float4*)(out_mv + (size_t)t * ROW_MV + 8 * lane);
        dst[0] = o0;
        dst[1] = o1;

        hh0[u] = h0 * invd;
        hh1[u] = h1 * invd;
        sSK[tl * SK_STRIDE + lane] = sc_skip[(size_t)t * SSC + lane];
    }
    __syncwarp();

    // ---------------- Phase 3a: hidden = gelu(interp_h + skip@W1b + b1) -----
    {
        float2 bb = __ldg((const float2*)(b1_s + 2 * lane));
        float a0x = bb.x + hh0[0], a0y = bb.y + hh1[0];
        float a1x = bb.x + hh0[1], a1y = bb.y + hh1[1];
        float a2x = bb.x + hh0[2], a2y = bb.y + hh1[2];
        float a3x = bb.x + hh0[3], a3y = bb.y + hh1[3];
        const float* x0 = sSK + (r0 + 0) * SK_STRIDE;
        const float* x1 = sSK + (r0 + 1) * SK_STRIDE;
        const float* x2 = sSK + (r0 + 2) * SK_STRIDE;
        const float* x3 = sSK + (r0 + 3) * SK_STRIDE;
        #pragma unroll
        for (int jc = 0; jc < 8; jc++) {
            float4 v0 = *(const float4*)(x0 + 4 * jc);
            float4 v1 = *(const float4*)(x1 + 4 * jc);
            float4 v2 = *(const float4*)(x2 + 4 * jc);
            float4 v3 = *(const float4*)(x3 + 4 * jc);
            #pragma unroll
            for (int r = 0; r < 4; r++) {
                const int j = 4 * jc + r;
                __half2 wh = __ldg((const __half2*)(g_w1bh + j * HID + 2 * lane));
                float2 wv = __half22float2(wh);
                const float e0 = (r == 0) ? v0.x : (r == 1) ? v0.y : (r == 2) ? v0.z : v0.w;
                const float e1 = (r == 0) ? v1.x : (r == 1) ? v1.y : (r == 2) ? v1.z : v1.w;
                const float e2 = (r == 0) ? v2.x : (r == 1) ? v2.y : (r == 2) ? v2.z : v2.w;
                const float e3 = (r == 0) ? v3.x : (r == 1) ? v3.y : (r == 2) ? v3.z : v3.w;
                a0x = fmaf(e0, wv.x, a0x); a0y = fmaf(e0, wv.y, a0y);
                a1x = fmaf(e1, wv.x, a1x); a1y = fmaf(e1, wv.y, a1y);
                a2x = fmaf(e2, wv.x, a2x); a2y = fmaf(e2, wv.y, a2y);
                a3x = fmaf(e3, wv.x, a3x); a3y = fmaf(e3, wv.y, a3y);
            }
        }
        *(float2*)(sHA + (r0 + 0) * HA_STRIDE + 2 * lane) = make_float2(gelu_tanh(a0x), gelu_tanh(a0y));
        *(float2*)(sHA + (r0 + 1) * HA_STRIDE + 2 * lane) = make_float2(gelu_tanh(a1x), gelu_tanh(a1y));
        *(float2*)(sHA + (r0 + 2) * HA_STRIDE + 2 * lane) = make_float2(gelu_tanh(a2x), gelu_tanh(a2y));
        *(float2*)(sHA + (r0 + 3) * HA_STRIDE + 2 * lane) = make_float2(gelu_tanh(a3x), gelu_tanh(a3y));
    }
    __syncwarp();

    // ---------------- Phase 3b: scalar output (lane = channel, packed fp16 W2)
    {
        const float bb = __ldg(b2_s + lane);
        float a0 = bb, a1 = bb, a2 = bb, a3 = bb;
        const float* h0 = sHA + (r0 + 0) * HA_STRIDE;
        const float* h1 = sHA + (r0 + 1) * HA_STRIDE;
        const float* h2 = sHA + (r0 + 2) * HA_STRIDE;
        const float* h3 = sHA + (r0 + 3) * HA_STRIDE;
        #pragma unroll
        for (int hc = 0; hc < 8; hc++) {
            uint4 wv = __ldg((const uint4*)(g_w2p + hc * 256 + lane * 8));
            const __half2* wh = (const __half2*)&wv;
            float2 wf0 = __half22float2(wh[0]);
            float2 wf1 = __half22float2(wh[1]);
            float2 wf2 = __half22float2(wh[2]);
            float2 wf3 = __half22float2(wh[3]);
            float4 va0 = *(const float4*)(h0 + 8 * hc);
            float4 vb0 = *(const float4*)(h0 + 8 * hc + 4);
            float4 va1 = *(const float4*)(h1 + 8 * hc);
            float4 vb1 = *(const float4*)(h1 + 8 * hc + 4);
            float4 va2 = *(const float4*)(h2 + 8 * hc);
            float4 vb2 = *(const float4*)(h2 + 8 * hc + 4);
            float4 va3 = *(const float4*)(h3 + 8 * hc);
            float4 vb3 = *(const float4*)(h3 + 8 * hc + 4);
            a0 = fmaf(va0.x, wf0.x, a0); a0 = fmaf(va0.y, wf0.y, a0);
            a0 = fmaf(va0.z, wf1.x, a0); a0 = fmaf(va0.w, wf1.y, a0);
            a0 = fmaf(vb0.x, wf2.x, a0); a0 = fmaf(vb0.y, wf2.y, a0);
            a0 = fmaf(vb0.z, wf3.x, a0); a0 = fmaf(vb0.w, wf3.y, a0);
            a1 = fmaf(va1.x, wf0.x, a1); a1 = fmaf(va1.y, wf0.y, a1);
            a1 = fmaf(va1.z, wf1.x, a1); a1 = fmaf(va1.w, wf1.y, a1);
            a1 = fmaf(vb1.x, wf2.x, a1); a1 = fmaf(vb1.y, wf2.y, a1);
            a1 = fmaf(vb1.z, wf3.x, a1); a1 = fmaf(vb1.w, wf3.y, a1);
            a2 = fmaf(va2.x, wf0.x, a2); a2 = fmaf(va2.y, wf0.y, a2);
            a2 = fmaf(va2.z, wf1.x, a2); a2 = fmaf(va2.w, wf1.y, a2);
            a2 = fmaf(vb2.x, wf2.x, a2); a2 = fmaf(vb2.y, wf2.y, a2);
            a2 = fmaf(vb2.z, wf3.x, a2); a2 = fmaf(vb2.w, wf3.y, a2);
            a3 = fmaf(va3.x, wf0.x, a3); a3 = fmaf(va3.y, wf0.y, a3);
            a3 = fmaf(va3.z, wf1.x, a3); a3 = fmaf(va3.w, wf1.y, a3);
            a3 = fmaf(vb3.x, wf2.x, a3); a3 = fmaf(vb3.y, wf2.y, a3);
            a3 = fmaf(vb3.z, wf3.x, a3); a3 = fmaf(vb3.w, wf3.y, a3);
        }
        out_sc[(size_t)(tbase + r0 + 0) * SSC + lane] = a0;
        out_sc[(size_t)(tbase + r0 + 1) * SSC + lane] = a1;
        out_sc[(size_t)(tbase + r0 + 2) * SSC + lane] = a2;
        out_sc[(size_t)(tbase + r0 + 3) * SSC + lane] = a3;
    }
}

// ---------------------------------------------------------------------------
extern "C" void kernel_launch(void* const* d_in, const int* in_sizes, int n_in,
                              void* d_out, int out_size)
{
    const float* mv_src   = (const float*)d_in[0];
    const float* mv_skip  = (const float*)d_in[1];
    const float* sc_src   = (const float*)d_in[2];
    const float* sc_skip  = (const float*)d_in[3];
    const float* pos_src  = (const float*)d_in[4];
    const float* pos_tgt  = (const float*)d_in[5];
    const int*   isrc     = (const int*)d_in[6];
    const float* W1_mv    = (const float*)d_in[8];
    const float* W2_mv    = (const float*)d_in[9];
    const float* W1_s     = (const float*)d_in[10];
    const float* b1_s     = (const float*)d_in[11];
    const float* W2_s     = (const float*)d_in[12];
    const float* b2_s     = (const float*)d_in[13];

    float* out_mv = (float*)d_out;
    float* out_sc = out_mv + (size_t)N_TGT * CCH * MVD;

    prep_all<<<N_SRC / PREP_ROWS, 256>>>(mv_src, sc_src, W1_mv, W2_mv, W1_s, W2_s);
    fused_kernel<<<N_TGT / TGT_PER_BLOCK, TPB>>>(
        mv_skip, sc_skip, pos_src, pos_tgt, isrc,
        b1_s, b2_s, out_mv, out_sc);
}

// round 16
// speedup vs baseline: 1.0595x; 1.0595x over previous
#include <cuda_runtime.h>
#include <cuda_fp16.h>
#include <cstddef>

#define N_SRC   16384
#define N_TGT   65536
#define KNBR    8
#define CCH     16
#define CSKIP   2
#define SSC     32
#define HID     64
#define MVD     16
#define ROW_MV  (CCH*MVD)      // 256
#define TPB     128
#define TGT_PER_BLOCK 16
#define HA_STRIDE 68
#define SK_STRIDE 36
#define PREP_ROWS 32           // source rows per block -> 512 blocks (single wave)

__device__ __half g_mvTh[(size_t)N_SRC * ROW_MV]; // mv_src @ Weff[0:16]  (8 MB fp16)
__device__ __half g_scTh[(size_t)N_SRC * HID];    // sc_src @ W1a         (2 MB fp16)
__device__ __half g_w1bh[SSC * HID];              // W1_s rows 32..63 fp16
__device__ __half g_w2p[HID * SSC];               // W2 packed: [hc][ch][r] fp16
__device__ float  g_wsk[2 * CCH];                 // Weff rows 16,17

typedef unsigned long long ull;

__device__ __forceinline__ ull pack2(float lo, float hi)
{
    ull r;
    asm("mov.b64 %0, {%1, %2};" : "=l"(r) : "r"(__float_as_uint(lo)), "r"(__float_as_uint(hi)));
    return r;
}
__device__ __forceinline__ void unpack2(ull v, float& lo, float& hi)
{
    unsigned a, b;
    asm("mov.b64 {%0, %1}, %2;" : "=r"(a), "=r"(b) : "l"(v));
    lo = __uint_as_float(a);
    hi = __uint_as_float(b);
}
__device__ __forceinline__ void ffma2(ull& d, ull a, ull b)
{
    asm("fma.rn.f32x2 %0, %1, %2, %3;" : "=l"(d) : "l"(a), "l"(b), "l"(d));
}

__device__ __forceinline__ float gelu_tanh(float x)
{
    const float c0 = 0.7978845608028654f;
    float u = c0 * fmaf(0.044715f * x, x * x, x);
    float t = tanhf(u);
    return 0.5f * x * (1.0f + t);
}

// ---------------------------------------------------------------------------
// Prep: 512 blocks x 256 thr, 32 rows each. Transforms in fma.rn.f32x2.
// (unchanged from R15 — at its DRAM/launch floor)
// ---------------------------------------------------------------------------
__global__ __launch_bounds__(256) void prep_all(
    const float* __restrict__ mv_src, const float* __restrict__ sc_src,
    const float* __restrict__ W1_mv,  const float* __restrict__ W2_mv,
    const float* __restrict__ W1_s,   const float* __restrict__ W2_s)
{
    __shared__ __align__(16) float rows[8 * 256];        // 8 KB (chunk of 8 rows)
    __shared__ __align__(16) float we[CCH * CCH];        // 1 KB
    __shared__ __align__(16) float xs[PREP_ROWS * 34];   // 4.25 KB
    __shared__ __align__(16) float wT[HID * 34];         // 8.5 KB  W1a transposed [h][j]
    __shared__ __align__(16) float w2T[CCH * 66];        // 4.1 KB  W2_mv transposed [c][h]

    const int tid = threadIdx.x;
    const int s0  = blockIdx.x * PREP_ROWS;

    const float4* msrc = (const float4*)(mv_src + (size_t)s0 * 256);
    ((float4*)rows)[tid]       = __ldg(msrc + tid);
    ((float4*)rows)[tid + 256] = __ldg(msrc + tid + 256);
    #pragma unroll
    for (int i = 0; i < 4; i++) {
        const int idx = tid + 256 * i;
        xs[(idx >> 5) * 34 + (idx & 31)] = __ldg(sc_src + (size_t)s0 * SSC + idx);
    }
    #pragma unroll
    for (int i = 0; i < 8; i++) {
        const int idx = tid + 256 * i;
        wT[(idx & 63) * 34 + (idx >> 6)] = __ldg(W1_s + idx);
    }
    #pragma unroll
    for (int i = 0; i < 4; i++) {
        const int idx = tid + 256 * i;
        w2T[(idx & 15) * 66 + (idx >> 4)] = __ldg(W2_mv + idx);
    }
    if (blockIdx.x == 0) {
        #pragma unroll
        for (int i = 0; i < 8; i++) {
            const int idx = tid + 256 * i;
            g_w1bh[idx] = __float2half_rn(__ldg(W1_s + SSC * HID + idx));
            const int hc = idx >> 8, ch = (idx >> 3) & 31, r = idx & 7;
            g_w2p[idx] = __float2half_rn(__ldg(W2_s + (hc * 8 + r) * SSC + ch));
        }
        if (tid < 32) {
            const int cp = 16 + (tid >> 4), c = tid & 15;
            float acc = 0.f;
            #pragma unroll
            for (int h = 0; h < HID; h++)
                acc = fmaf(__ldg(W1_mv + cp * HID + h), __ldg(W2_mv + h * CCH + c), acc);
            g_wsk[tid] = acc;
        }
    }
    __syncthreads();

    float4 pf0 = __ldg(msrc + 512 + tid);
    float4 pf1 = __ldg(msrc + 512 + tid + 256);
    {
        const int cp = tid >> 4, c = tid & 15;
        ull a2 = 0ULL;
        #pragma unroll
        for (int hp = 0; hp < 32; hp++) {
            ull w1p = __ldg((const ull*)(W1_mv + cp * HID + 2 * hp));
            ull w2p = *(const ull*)(w2T + c * 66 + 2 * hp);
            ffma2(a2, w1p, w2p);
        }
        float e, o;
        unpack2(a2, e, o);
        we[tid] = e + o;
    }
    __syncthreads();

    const int mrow = tid >> 5;
    const int c2   = (tid & 31) >> 1;
    const int i0   = (tid & 1) * 8;
    #pragma unroll
    for (int ch = 0; ch < 4; ch++) {
        {
            const float* row = rows + mrow * 256;
            ull acc2[4] = {0ULL, 0ULL, 0ULL, 0ULL};
            #pragma unroll
            for (int cp = 0; cp < 16; cp++) {
                const ull wv2 = pack2(we[cp * 16 + c2], we[cp * 16 + c2]);
                const ulonglong2* rp = (const ulonglong2*)(row + cp * 16 + i0);
                ulonglong2 pa = rp[0], pb = rp[1];
                ffma2(acc2[0], pa.x, wv2);
                ffma2(acc2[1], pa.y, wv2);
                ffma2(acc2[2], pb.x, wv2);
                ffma2(acc2[3], pb.y, wv2);
            }
            __half2 h2[4];
            #pragma unroll
            for (int p = 0; p < 4; p++) {
                float lo, hi;
                unpack2(acc2[p], lo, hi);
                h2[p] = __floats2half2_rn(lo, hi);
            }
            *(uint4*)(g_mvTh + (size_t)(s0 + ch * 8 + mrow) * 256 + c2 * 16 + i0) =
                *(const uint4*)h2;
        }
        if (ch < 3) {
            __syncthreads();
            ((float4*)rows)[tid]       = pf0;
            ((float4*)rows)[tid + 256] = pf1;
            if (ch < 2) {
                pf0 = __ldg(msrc + 512 * (ch + 2) + tid);
                pf1 = __ldg(msrc + 512 * (ch + 2) + tid + 256);
            }
            __syncthreads();
        }
    }

    {
        const int h  = tid & 63;
        const int rg = tid >> 6;
        #pragma unroll
        for (int half = 0; half < 2; half++) {
            const int rb = rg * 8 + half * 4;
            ull acc2[4] = {0ULL, 0ULL, 0ULL, 0ULL};
            #pragma unroll
            for (int jp = 0; jp < 16; jp++) {
                const ull wp = *(const ull*)(wT + h * 34 + 2 * jp);
                #pragma unroll
                for (int r = 0; r < 4; r++) {
                    const ull xp = *(const ull*)(xs + (rb + r) * 34 + 2 * jp);
                    ffma2(acc2[r], xp, wp);
                }
            }
            #pragma unroll
            for (int r = 0; r < 4; r++) {
                float e, o;
                unpack2(acc2[r], e, o);
                g_scTh[(size_t)(s0 + rb + r) * HID + h] = __float2half_rn(e + o);
            }
        }
    }
}

// ---------------------------------------------------------------------------
// Warp-private pipeline. OCCUPANCY PROBE: launch_bounds min-blocks 6 -> 7
// (forces regs 80 -> <=73; 24 -> 28 warps/SM).
// ---------------------------------------------------------------------------
__global__ __launch_bounds__(TPB, 7) void fused_kernel(
    const float* __restrict__ mv_skip, const float* __restrict__ sc_skip,
    const float* __restrict__ pos_src, const float* __restrict__ pos_tgt,
    const int*   __restrict__ isrc,
    const float* __restrict__ b1_s,    const float* __restrict__ b2_s,
    float* __restrict__ out_mv,        float* __restrict__ out_sc)
{
    __shared__ __align__(16) float sHA[TGT_PER_BLOCK * HA_STRIDE];
    __shared__ __align__(16) float sSK[TGT_PER_BLOCK * SK_STRIDE];

    const int tid  = threadIdx.x;
    const int lane = tid & 31;
    const int warp = tid >> 5;
    const int tbase = blockIdx.x * TGT_PER_BLOCK;
    const int r0 = warp * 4;

    const int cch = lane >> 1;
    const float w16 = __ldg(g_wsk + cch);
    const float w17 = __ldg(g_wsk + 16 + cch);

    float hh0[4], hh1[4];

    // ---------------- Phase 1: IDW gather of fp16 transformed sources -------
    #pragma unroll
    for (int u = 0; u < 4; u++) {
        const int tl = r0 + u;
        const int t  = tbase + tl;

        float wk = 0.f;
        int   sk = 0;
        if (lane < KNBR) {
            sk = isrc[t * KNBR + lane];
            float dx = pos_src[sk * 3 + 0] - pos_tgt[t * 3 + 0];
            float dy = pos_src[sk * 3 + 1] - pos_tgt[t * 3 + 1];
            float dz = pos_src[sk * 3 + 2] - pos_tgt[t * 3 + 2];
            float d2 = fmaf(dx, dx, fmaf(dy, dy, dz * dz));
            d2 = fmaxf(d2, 1e-16f);
            wk = 1.0f / d2;
        }
        float den = wk;
        #pragma unroll
        for (int o = 16; o; o >>= 1) den += __shfl_xor_sync(0xffffffffu, den, o);
        const float invd = 1.0f / den;

        float acc[8];
        #pragma unroll
        for (int j = 0; j < 8; j++) acc[j] = 0.f;
        float h0 = 0.f, h1 = 0.f;

        #pragma unroll
        for (int k = 0; k < KNBR; k++) {
            const float w = __shfl_sync(0xffffffffu, wk, k);
            const int   s = __shfl_sync(0xffffffffu, sk, k);
            uint4 v = __ldg((const uint4*)(g_mvTh + (size_t)s * ROW_MV) + lane);
            const __half2* hv = (const __half2*)&v;
            float2 f0 = __half22float2(hv[0]);
            float2 f1 = __half22float2(hv[1]);
            float2 f2 = __half22float2(hv[2]);
            float2 f3 = __half22float2(hv[3]);
            acc[0] = fmaf(w, f0.x, acc[0]); acc[1] = fmaf(w, f0.y, acc[1]);
            acc[2] = fmaf(w, f1.x, acc[2]); acc[3] = fmaf(w, f1.y, acc[3]);
            acc[4] = fmaf(w, f2.x, acc[4]); acc[5] = fmaf(w, f2.y, acc[5]);
            acc[6] = fmaf(w, f3.x, acc[6]); acc[7] = fmaf(w, f3.y, acc[7]);
            __half2 sv = __ldg((const __half2*)(g_scTh + (size_t)s * HID) + lane);
            float2 sf = __half22float2(sv);
            h0 = fmaf(w, sf.x, h0); h1 = fmaf(w, sf.y, h1);
        }

        const int ib = (lane & 1) * 8;
        float4 s0a = __ldg((const float4*)(mv_skip + (size_t)t * 32 + ib));
        float4 s0b = __ldg((const float4*)(mv_skip + (size_t)t * 32 + ib + 4));
        float4 s1a = __ldg((const float4*)(mv_skip + (size_t)t * 32 + 16 + ib));
        float4 s1b = __ldg((const float4*)(mv_skip + (size_t)t * 32 + 16 + ib + 4));

        float4 o0, o1;
        o0.x = fmaf(acc[0], invd, fmaf(s0a.x, w16, s1a.x * w17));
        o0.y = fmaf(acc[1], invd, fmaf(s0a.y, w16, s1a.y * w17));
        o0.z = fmaf(acc[2], invd, fmaf(s0a.z, w16, s1a.z * w17));
        o0.w = fmaf(acc[3], invd, fmaf(s0a.w, w16, s1a.w * w17));
        o1.x = fmaf(acc[4], invd, fmaf(s0b.x, w16, s1b.x * w17));
        o1.y = fmaf(acc[5], invd, fmaf(s0b.y, w16, s1b.y * w17));
        o1.z = fmaf(acc[6], invd, fmaf(s0b.z, w16, s1b.z * w17));
        o1.w = fmaf(acc[7], invd, fmaf(s0b.w, w16, s1b.w * w17));

        float4* dst = (float4*)(out_mv + (size_t)t * ROW_MV + 8 * lane);
        dst[0] = o0;
        dst[1] = o1;

        hh0[u] = h0 * invd;
        hh1[u] = h1 * invd;
        sSK[tl * SK_STRIDE + lane] = sc_skip[(size_t)t * SSC + lane];
    }
    __syncwarp();

    // ---------------- Phase 3a: hidden = gelu(interp_h + skip@W1b + b1) -----
    {
        float2 bb = __ldg((const float2*)(b1_s + 2 * lane));
        float a0x = bb.x + hh0[0], a0y = bb.y + hh1[0];
        float a1x = bb.x + hh0[1], a1y = bb.y + hh1[1];
        float a2x = bb.x + hh0[2], a2y = bb.y + hh1[2];
        float a3x = bb.x + hh0[3], a3y = bb.y + hh1[3];
        const float* x0 = sSK + (r0 + 0) * SK_STRIDE;
        const float* x1 = sSK + (r0 + 1) * SK_STRIDE;
        const float* x2 = sSK + (r0 + 2) * SK_STRIDE;
        const float* x3 = sSK + (r0 + 3) * SK_STRIDE;
        #pragma unroll
        for (int jc = 0; jc < 8; jc++) {
            float4 v0 = *(const float4*)(x0 + 4 * jc);
            float4 v1 = *(const float4*)(x1 + 4 * jc);
            float4 v2 = *(const float4*)(x2 + 4 * jc);
            float4 v3 = *(const float4*)(x3 + 4 * jc);
            #pragma unroll
            for (int r = 0; r < 4; r++) {
                const int j = 4 * jc + r;
                __half2 wh = __ldg((const __half2*)(g_w1bh + j * HID + 2 * lane));
                float2 wv = __half22float2(wh);
                const float e0 = (r == 0) ? v0.x : (r == 1) ? v0.y : (r == 2) ? v0.z : v0.w;
                const float e1 = (r == 0) ? v1.x : (r == 1) ? v1.y : (r == 2) ? v1.z : v1.w;
                const float e2 = (r == 0) ? v2.x : (r == 1) ? v2.y : (r == 2) ? v2.z : v2.w;
                const float e3 = (r == 0) ? v3.x : (r == 1) ? v3.y : (r == 2) ? v3.z : v3.w;
                a0x = fmaf(e0, wv.x, a0x); a0y = fmaf(e0, wv.y, a0y);
                a1x = fmaf(e1, wv.x, a1x); a1y = fmaf(e1, wv.y, a1y);
                a2x = fmaf(e2, wv.x, a2x); a2y = fmaf(e2, wv.y, a2y);
                a3x = fmaf(e3, wv.x, a3x); a3y = fmaf(e3, wv.y, a3y);
            }
        }
        *(float2*)(sHA + (r0 + 0) * HA_STRIDE + 2 * lane) = make_float2(gelu_tanh(a0x), gelu_tanh(a0y));
        *(float2*)(sHA + (r0 + 1) * HA_STRIDE + 2 * lane) = make_float2(gelu_tanh(a1x), gelu_tanh(a1y));
        *(float2*)(sHA + (r0 + 2) * HA_STRIDE + 2 * lane) = make_float2(gelu_tanh(a2x), gelu_tanh(a2y));
        *(float2*)(sHA + (r0 + 3) * HA_STRIDE + 2 * lane) = make_float2(gelu_tanh(a3x), gelu_tanh(a3y));
    }
    __syncwarp();

    // ---------------- Phase 3b: scalar output (lane = channel, packed fp16 W2)
    {
        const float bb = __ldg(b2_s + lane);
        float a0 = bb, a1 = bb, a2 = bb, a3 = bb;
        const float* h0 = sHA + (r0 + 0) * HA_STRIDE;
        const float* h1 = sHA + (r0 + 1) * HA_STRIDE;
        const float* h2 = sHA + (r0 + 2) * HA_STRIDE;
        const float* h3 = sHA + (r0 + 3) * HA_STRIDE;
        #pragma unroll
        for (int hc = 0; hc < 8; hc++) {
            uint4 wv = __ldg((const uint4*)(g_w2p + hc * 256 + lane * 8));
            const __half2* wh = (const __half2*)&wv;
            float2 wf0 = __half22float2(wh[0]);
            float2 wf1 = __half22float2(wh[1]);
            float2 wf2 = __half22float2(wh[2]);
            float2 wf3 = __half22float2(wh[3]);
            float4 va0 = *(const float4*)(h0 + 8 * hc);
            float4 vb0 = *(const float4*)(h0 + 8 * hc + 4);
            float4 va1 = *(const float4*)(h1 + 8 * hc);
            float4 vb1 = *(const float4*)(h1 + 8 * hc + 4);
            float4 va2 = *(const float4*)(h2 + 8 * hc);
            float4 vb2 = *(const float4*)(h2 + 8 * hc + 4);
            float4 va3 = *(const float4*)(h3 + 8 * hc);
            float4 vb3 = *(const float4*)(h3 + 8 * hc + 4);
            a0 = fmaf(va0.x, wf0.x, a0); a0 = fmaf(va0.y, wf0.y, a0);
            a0 = fmaf(va0.z, wf1.x, a0); a0 = fmaf(va0.w, wf1.y, a0);
            a0 = fmaf(vb0.x, wf2.x, a0); a0 = fmaf(vb0.y, wf2.y, a0);
            a0 = fmaf(vb0.z, wf3.x, a0); a0 = fmaf(vb0.w, wf3.y, a0);
            a1 = fmaf(va1.x, wf0.x, a1); a1 = fmaf(va1.y, wf0.y, a1);
            a1 = fmaf(va1.z, wf1.x, a1); a1 = fmaf(va1.w, wf1.y, a1);
            a1 = fmaf(vb1.x, wf2.x, a1); a1 = fmaf(vb1.y, wf2.y, a1);
            a1 = fmaf(vb1.z, wf3.x, a1); a1 = fmaf(vb1.w, wf3.y, a1);
            a2 = fmaf(va2.x, wf0.x, a2); a2 = fmaf(va2.y, wf0.y, a2);
            a2 = fmaf(va2.z, wf1.x, a2); a2 = fmaf(va2.w, wf1.y, a2);
            a2 = fmaf(vb2.x, wf2.x, a2); a2 = fmaf(vb2.y, wf2.y, a2);
            a2 = fmaf(vb2.z, wf3.x, a2); a2 = fmaf(vb2.w, wf3.y, a2);
            a3 = fmaf(va3.x, wf0.x, a3); a3 = fmaf(va3.y, wf0.y, a3);
            a3 = fmaf(va3.z, wf1.x, a3); a3 = fmaf(va3.w, wf1.y, a3);
            a3 = fmaf(vb3.x, wf2.x, a3); a3 = fmaf(vb3.y, wf2.y, a3);
            a3 = fmaf(vb3.z, wf3.x, a3); a3 = fmaf(vb3.w, wf3.y, a3);
        }
        out_sc[(size_t)(tbase + r0 + 0) * SSC + lane] = a0;
        out_sc[(size_t)(tbase + r0 + 1) * SSC + lane] = a1;
        out_sc[(size_t)(tbase + r0 + 2) * SSC + lane] = a2;
        out_sc[(size_t)(tbase + r0 + 3) * SSC + lane] = a3;
    }
}

// ---------------------------------------------------------------------------
extern "C" void kernel_launch(void* const* d_in, const int* in_sizes, int n_in,
                              void* d_out, int out_size)
{
    const float* mv_src   = (const float*)d_in[0];
    const float* mv_skip  = (const float*)d_in[1];
    const float* sc_src   = (const float*)d_in[2];
    const float* sc_skip  = (const float*)d_in[3];
    const float* pos_src  = (const float*)d_in[4];
    const float* pos_tgt  = (const float*)d_in[5];
    const int*   isrc     = (const int*)d_in[6];
    const float* W1_mv    = (const float*)d_in[8];
    const float* W2_mv    = (const float*)d_in[9];
    const float* W1_s     = (const float*)d_in[10];
    const float* b1_s     = (const float*)d_in[11];
    const float* W2_s     = (const float*)d_in[12];
    const float* b2_s     = (const float*)d_in[13];

    float* out_mv = (float*)d_out;
    float* out_sc = out_mv + (size_t)N_TGT * CCH * MVD;

    prep_all<<<N_SRC / PREP_ROWS, 256>>>(mv_src, sc_src, W1_mv, W2_mv, W1_s, W2_s);
    fused_kernel<<<N_TGT / TGT_PER_BLOCK, TPB>>>(
        mv_skip, sc_skip, pos_src, pos_tgt, isrc,
        b1_s, b2_s, out_mv, out_sc);
}